// round 12
// baseline (speedup 1.0000x reference)
#include <cuda_runtime.h>
#include <cuda_fp16.h>
#include <stdint.h>

#define MAXN    1048576        // >= 1,000,000 rows
#define KTAPS   27
#define CIN     32
#define COUT    32
#define MBLOCK  384            // rows per tile (12 warps x 32 rows)
#define NTHREADS 384
#define NWARP   12
#define NSTAGE  5              // smem gather stages per warp (4 taps in flight)

// Scratch (allocation-free): fp16 copy of X with permuted channel pairs, fp16 W.
__device__ __align__(128) __half g_x16[(size_t)MAXN * CIN];           // 64 MiB
__device__ __align__(16) __half g_w16[KTAPS * COUT * CIN];            // [tap][n][k'] 54 KiB
__device__ int g_nbr_is64;                                            // neighbor dtype flag

// Involution on channel-pair index (s in 0..15): sigma(sigma(s)) == s
__device__ __forceinline__ int sigma(int s) { return ((s & 3) << 2) | (s >> 2); }

__device__ __forceinline__ uint32_t smem_u32(const void* p) {
    uint32_t a;
    asm("{ .reg .u64 t; cvta.to.shared.u64 t, %1; cvt.u32.u64 %0, t; }" : "=r"(a) : "l"(p));
    return a;
}

template <int N>
__device__ __forceinline__ void waitg() {
    asm volatile("cp.async.wait_group %0;" :: "n"(N) : "memory");
}

// ---------------- Fused prep: X convert + W convert + nbr dtype detect ----------------
__global__ void prep_kernel(const float* __restrict__ x,
                            const float* __restrict__ w,
                            const int*   __restrict__ nbr_words, int n) {
    // X conversion: fp32 [N,32] -> fp16 permuted [N,32]
    long long tid = (long long)blockIdx.x * blockDim.x + threadIdx.x;
    long long total = (long long)n * 16;
    if (tid < total) {
        int i = (int)(tid >> 4);
        int s = (int)(tid & 15);
        int p = sigma(s);
        float2 v = __ldcs((const float2*)(x + (size_t)i * CIN + 2 * p));
        ((__half2*)g_x16)[(size_t)i * 16 + s] = __floats2half2_rn(v.x, v.y);
    }
    // W conversion (first 108 blocks)
    if (blockIdx.x < (KTAPS * COUT * CIN + 255) / 256) {
        int e = blockIdx.x * 256 + threadIdx.x;
        if (e < KTAPS * COUT * CIN) {
            int tap = e / (COUT * CIN);
            int rem = e % (COUT * CIN);
            int nn  = rem / CIN;
            int kp  = rem % CIN;
            int s   = kp >> 1, bit = kp & 1;
            int c   = 2 * sigma(s) + bit;
            g_w16[e] = __float2half_rn(w[(size_t)tap * CIN * COUT + (size_t)c * COUT + nn]);
        }
    }
    // nbr dtype detect (block 0): int64 LE nonneg -> odd int32 words all zero
    if (blockIdx.x == 0) {
        int nz = 0;
        #pragma unroll
        for (int j = 0; j < 8; j++)
            nz |= nbr_words[2 * (threadIdx.x * 8 + j) + 1];
        int any = __syncthreads_or(nz != 0);
        if (threadIdx.x == 0) g_nbr_is64 = any ? 0 : 1;
    }
}

// ---------------- fp16 MMA m16n8k16, fp32 accumulate ----------------
__device__ __forceinline__ void mma16816(float c[4],
                                         uint32_t a0, uint32_t a1, uint32_t a2, uint32_t a3,
                                         uint32_t b0, uint32_t b1) {
    asm("mma.sync.aligned.m16n8k16.row.col.f32.f16.f16.f32 "
        "{%0,%1,%2,%3}, {%4,%5,%6,%7}, {%8,%9}, {%0,%1,%2,%3};\n"
        : "+f"(c[0]), "+f"(c[1]), "+f"(c[2]), "+f"(c[3])
        : "r"(a0), "r"(a1), "r"(a2), "r"(a3), "r"(b0), "r"(b1));
}

// ---------------- Main: persistent, cp.async depth-4 gather pipeline ----------------
// smem: [0, 55296)        fp16 W (uint4 view, [tap][128 x 16B])
//       [55296, 96768)    int32 neighbor BYTE OFFSETS (idx*64) [384 rows][27 taps]
//       [96768, 219648)   gather stages: 12 warps x 5 stages x 2048 B (32 rows x 64 B)
#define W_SMEM     55296
#define NBR_OFF    55296
#define GB_OFF     96768
#define SMEM_BYTES (GB_OFF + NWARP * NSTAGE * 2048)   // 219648

__global__ __launch_bounds__(NTHREADS, 1)
void conv_main_kernel(const void* __restrict__ nbr_raw,
                      const float* __restrict__ bias,
                      float* __restrict__ out, int n, int ntiles) {
    extern __shared__ uint8_t smem[];
    uint4* w_s4  = (uint4*)smem;
    int*   nbr_s = (int*)(smem + NBR_OFF);

    const int tid  = threadIdx.x;
    const int is64 = g_nbr_is64;

    // Stage W once per persistent block (3456 uint4, coalesced: 9 per thread)
    const uint4* wg4 = (const uint4*)g_w16;
    #pragma unroll
    for (int t = tid; t < 3456; t += NTHREADS) w_s4[t] = wg4[t];

    const int lane = tid & 31;
    const int warp = tid >> 5;
    const int q    = lane & 3;     // 16B chunk within 64B row
    const int nrow = lane >> 2;    // 0..7
    const int mb   = warp * 32;    // warp's 32 rows within tile

    // This thread's gather-buffer addresses (stage s adds s*2048; row j adds j*512)
    const uint32_t gw  = smem_u32(smem) + GB_OFF + warp * (NSTAGE * 2048) + nrow * 64 + q * 16;
    const uint8_t* gwp = smem + GB_OFF + warp * (NSTAGE * 2048) + nrow * 64 + q * 16;
    const char*    xg  = (const char*)g_x16 + q * 16;

    float2 bz[4];
    #pragma unroll
    for (int t = 0; t < 4; t++)
        bz[t] = *(const float2*)(bias + t * 8 + 2 * q);

    // Issue one tap's gather for this thread's 4 rows (j=0..3 -> rows j*8+nrow) into stage st
    #define ISSUE(kk, st) do {                                                   \
        uint32_t d_ = gw + (st) * 2048;                                          \
        _Pragma("unroll")                                                        \
        for (int j = 0; j < 4; j++) {                                            \
            int off_ = nbr_s[(mb + j * 8 + nrow) * KTAPS + (kk)];                \
            asm volatile("cp.async.cg.shared.global [%0], [%1], 16;"             \
                         :: "r"(d_ + j * 512), "l"(xg + off_) : "memory");       \
        }                                                                        \
        asm volatile("cp.async.commit_group;" ::: "memory");                     \
    } while (0)

    // Read back this thread's own-written fragments from stage st
    #define RB(st, lo0, hi0, lo1, hi1) do {                                      \
        const uint8_t* sb_ = gwp + (st) * 2048;                                  \
        lo0 = *(const uint4*)(sb_);                                              \
        hi0 = *(const uint4*)(sb_ + 512);                                        \
        lo1 = *(const uint4*)(sb_ + 1024);                                       \
        hi1 = *(const uint4*)(sb_ + 1536);                                       \
    } while (0)

    #define MMA_T(k, lo0, hi0, lo1, hi1) do {                                    \
        _Pragma("unroll")                                                        \
        for (int t = 0; t < 4; t++) {                                            \
            uint4 bw = w_s4[(k) * 128 + (t * 8 + nrow) * 4 + q];                 \
            mma16816(acc[0][t], lo0.x, hi0.x, lo0.y, hi0.y, bw.x, bw.y);         \
            mma16816(acc[0][t], lo0.z, hi0.z, lo0.w, hi0.w, bw.z, bw.w);         \
            mma16816(acc[1][t], lo1.x, hi1.x, lo1.y, hi1.y, bw.x, bw.y);         \
            mma16816(acc[1][t], lo1.z, hi1.z, lo1.w, hi1.w, bw.z, bw.w);         \
        }                                                                        \
    } while (0)

    #define NXT(s) ((s) == NSTAGE - 1 ? 0 : (s) + 1)

    for (int tile = blockIdx.x; tile < ntiles; tile += gridDim.x) {
        const int i0 = tile * MBLOCK;
        const bool full = (i0 + MBLOCK <= n);

        __syncthreads();   // all warps drained previous tile before nbr_s overwrite
        // Stage neighbor byte-offsets (idx*64); 27 independent LDGs per thread.
        if (is64) {
            const long long* g = (const long long*)nbr_raw + (size_t)i0 * KTAPS;
            #pragma unroll
            for (int j = 0; j < KTAPS; j++) {
                int t = tid + j * NTHREADS;
                int r = t / KTAPS;
                int k = t - r * KTAPS;
                long long v = (full || i0 + r < n) ? __ldcs(g + t) : 0;
                nbr_s[k + r * KTAPS] = ((int)v) << 6;
            }
        } else {
            const int* g = (const int*)nbr_raw + (size_t)i0 * KTAPS;
            #pragma unroll
            for (int j = 0; j < KTAPS; j++) {
                int t = tid + j * NTHREADS;
                int r = t / KTAPS;
                int k = t - r * KTAPS;
                int v = (full || i0 + r < n) ? __ldcs(g + t) : 0;
                nbr_s[k + r * KTAPS] = v << 6;
            }
        }
        __syncthreads();

        float acc[2][4][4];
        #pragma unroll
        for (int t = 0; t < 4; t++)
            #pragma unroll
            for (int mt = 0; mt < 2; mt++) {
                acc[mt][t][0] = bz[t].x; acc[mt][t][1] = bz[t].y;
                acc[mt][t][2] = bz[t].x; acc[mt][t][3] = bz[t].y;
            }

        // Prologue: fill 4 stages (4 taps in flight)
        ISSUE(0, 0); ISSUE(1, 1); ISSUE(2, 2); ISSUE(3, 3);

        int stC = 0;        // consume stage
        int stI = 4;        // issue stage
        uint4 lo0, hi0, lo1, hi1;

        #pragma unroll 1
        for (int k = 0; k < KTAPS - 4; k++) {
            waitg<3>();                    // group k complete
            RB(stC, lo0, hi0, lo1, hi1);
            ISSUE(k + 4, stI);             // overwrites stage consumed at k-1 (safe: its LDS
                                           // completed before MMA(k-1), which precedes this)
            MMA_T(k, lo0, hi0, lo1, hi1);
            stC = NXT(stC); stI = NXT(stI);
        }
        // Drain: taps 23..26 with decreasing outstanding counts
        waitg<3>(); RB(stC, lo0, hi0, lo1, hi1); MMA_T(23, lo0, hi0, lo1, hi1); stC = NXT(stC);
        waitg<2>(); RB(stC, lo0, hi0, lo1, hi1); MMA_T(24, lo0, hi0, lo1, hi1); stC = NXT(stC);
        waitg<1>(); RB(stC, lo0, hi0, lo1, hi1); MMA_T(25, lo0, hi0, lo1, hi1); stC = NXT(stC);
        waitg<0>(); RB(stC, lo0, hi0, lo1, hi1); MMA_T(26, lo0, hi0, lo1, hi1);

        // Epilogue: streaming stores (bias already in acc)
        #pragma unroll
        for (int mt = 0; mt < 2; mt++)
            #pragma unroll
            for (int half = 0; half < 2; half++) {
                int r = i0 + mb + mt * 16 + nrow + half * 8;
                if (full || r < n) {
                    float* po = out + (size_t)r * COUT + 2 * q;
                    #pragma unroll
                    for (int t = 0; t < 4; t++) {
                        float2 v;
                        v.x = acc[mt][t][half * 2 + 0];
                        v.y = acc[mt][t][half * 2 + 1];
                        __stcs((float2*)(po + t * 8), v);
                    }
                }
            }
    }
}

// ---------------- Launch ----------------
extern "C" void kernel_launch(void* const* d_in, const int* in_sizes, int n_in,
                              void* d_out, int out_size) {
    const float* x    = (const float*)d_in[0];       // [N, 32] f32
    const float* w    = (const float*)d_in[1];       // [27, 32, 32] f32
    const float* bias = (const float*)d_in[2];       // [32] f32
    const void*  nbr  = d_in[3];                     // [N, 27] int32 OR int64 (detected)
    float*       out  = (float*)d_out;               // [N, 32] f32

    const int n = in_sizes[0] / CIN;
    const int ntiles = (n + MBLOCK - 1) / MBLOCK;

    int nsm = 148;
    cudaDeviceGetAttribute(&nsm, cudaDevAttrMultiProcessorCount, 0);
    int grid = nsm;
    if (grid > ntiles) grid = ntiles;

    cudaFuncSetAttribute(conv_main_kernel,
                         cudaFuncAttributeMaxDynamicSharedMemorySize, SMEM_BYTES);

    {
        long long total = (long long)n * 16;
        int blocks = (int)((total + 255) / 256);
        prep_kernel<<<blocks, 256>>>(x, w, (const int*)nbr, n);
    }
    conv_main_kernel<<<grid, NTHREADS, SMEM_BYTES>>>(nbr, bias, out, n, ntiles);
}

// round 13
// speedup vs baseline: 1.1302x; 1.1302x over previous
#include <cuda_runtime.h>
#include <cuda_fp16.h>
#include <stdint.h>

#define MAXN    1048576        // >= 1,000,000 rows
#define KTAPS   27
#define CIN     32
#define COUT    32
#define MBLOCK  256            // rows per tile (2 m16-tiles x 16 rows per warp)
#define NTHREADS 256

// Scratch (allocation-free): fp16 copy of X with permuted channel pairs, fp16 W.
__device__ __align__(128) __half g_x16[(size_t)MAXN * CIN];           // 64 MiB
__device__ __align__(16) __half g_w16[KTAPS * COUT * CIN];            // [tap][n][k'] 54 KiB
__device__ int g_nbr_is64;                                            // neighbor dtype flag

// Involution on channel-pair index (s in 0..15): sigma(sigma(s)) == s
__device__ __forceinline__ int sigma(int s) { return ((s & 3) << 2) | (s >> 2); }

// ---------------- Fused prep: X convert + W convert + nbr dtype detect ----------------
__global__ void prep_kernel(const float* __restrict__ x,
                            const float* __restrict__ w,
                            const int*   __restrict__ nbr_words, int n) {
    // X conversion: fp32 [N,32] -> fp16 permuted [N,32]
    long long tid = (long long)blockIdx.x * blockDim.x + threadIdx.x;
    long long total = (long long)n * 16;
    if (tid < total) {
        int i = (int)(tid >> 4);
        int s = (int)(tid & 15);
        int p = sigma(s);                      // memory slot s holds original pair sigma(s)
        float2 v = __ldcs((const float2*)(x + (size_t)i * CIN + 2 * p));
        ((__half2*)g_x16)[(size_t)i * 16 + s] = __floats2half2_rn(v.x, v.y);
    }
    // W conversion (first 108 blocks)
    if (blockIdx.x < (KTAPS * COUT * CIN + 255) / 256) {
        int e = blockIdx.x * 256 + threadIdx.x;
        if (e < KTAPS * COUT * CIN) {
            int tap = e / (COUT * CIN);
            int rem = e % (COUT * CIN);
            int nn  = rem / CIN;
            int kp  = rem % CIN;               // permuted k position
            int s   = kp >> 1, bit = kp & 1;
            int c   = 2 * sigma(s) + bit;      // original input channel
            g_w16[e] = __float2half_rn(w[(size_t)tap * CIN * COUT + (size_t)c * COUT + nn]);
        }
    }
    // nbr dtype detect (block 0): int64 LE nonneg -> odd int32 words all zero
    if (blockIdx.x == 0) {
        int nz = 0;
        #pragma unroll
        for (int j = 0; j < 8; j++)
            nz |= nbr_words[2 * (threadIdx.x * 8 + j) + 1];
        int any = __syncthreads_or(nz != 0);
        if (threadIdx.x == 0) g_nbr_is64 = any ? 0 : 1;
    }
}

// ---------------- fp16 MMA m16n8k16, fp32 accumulate ----------------
__device__ __forceinline__ void mma16816(float c[4],
                                         uint32_t a0, uint32_t a1, uint32_t a2, uint32_t a3,
                                         uint32_t b0, uint32_t b1) {
    asm("mma.sync.aligned.m16n8k16.row.col.f32.f16.f16.f32 "
        "{%0,%1,%2,%3}, {%4,%5,%6,%7}, {%8,%9}, {%0,%1,%2,%3};\n"
        : "+f"(c[0]), "+f"(c[1]), "+f"(c[2]), "+f"(c[3])
        : "r"(a0), "r"(a1), "r"(a2), "r"(a3), "r"(b0), "r"(b1));
}

// ---------------- Main: persistent blocks, gather + 27-tap MMA, depth-3 pipeline ----
// (R5/R11 structure; only change: pipeline depth 2 -> 3 via 4 rotating buffers,
//  mainloop fully unrolled so buffer indices are compile-time.)
// smem: [0, 55296)          fp16 W (uint4 view, [tap][n-tile-row][16B])
//       [55296, 82944)      int32 neighbor BYTE OFFSETS (idx*64) [256 rows][27 taps]
#define W_SMEM     55296
#define SMEM_BYTES (W_SMEM + MBLOCK * KTAPS * 4)

__global__ __launch_bounds__(NTHREADS, 2)
void conv_main_kernel(const void* __restrict__ nbr_raw,
                      const float* __restrict__ bias,
                      float* __restrict__ out, int n, int ntiles) {
    extern __shared__ uint8_t smem[];
    uint4* w_s4  = (uint4*)smem;
    int*   nbr_s = (int*)(smem + W_SMEM);

    const int tid  = threadIdx.x;
    const int is64 = g_nbr_is64;

    // Stage W once per persistent block (3456 uint4, coalesced)
    const uint4* wg4 = (const uint4*)g_w16;
    #pragma unroll 4
    for (int t = tid; t < 3456; t += NTHREADS) w_s4[t] = wg4[t];

    const int lane = tid & 31;
    const int warp = tid >> 5;
    const int q    = lane & 3;     // quad column (16B chunk within row)
    const int nrow = lane >> 2;    // 0..7
    const int mb   = warp * 32;    // warp's 32 rows within tile

    // Bias fragment (kept in regs across tiles)
    float2 bz[4];
    #pragma unroll
    for (int t = 0; t < 4; t++)
        bz[t] = *(const float2*)(bias + t * 8 + 2 * q);

    const char* xb = (const char*)g_x16 + q * 16;   // this thread's chunk base

    #define LOAD_TAP(buf, k) do {                                           \
        _Pragma("unroll")                                                   \
        for (int mt = 0; mt < 2; mt++) {                                    \
            int rlo = mb + mt * 16 + nrow;                                  \
            int olo = nbr_s[rlo * KTAPS + (k)];                             \
            int ohi = nbr_s[(rlo + 8) * KTAPS + (k)];                       \
            (buf)[mt * 2 + 0] = *(const uint4*)(xb + olo);                  \
            (buf)[mt * 2 + 1] = *(const uint4*)(xb + ohi);                  \
        }                                                                   \
    } while (0)

    #define MMA_TAP(buf, k) do {                                            \
        _Pragma("unroll")                                                   \
        for (int t = 0; t < 4; t++) {                                       \
            uint4 bw = w_s4[(k) * 128 + (t * 8 + nrow) * 4 + q];            \
            _Pragma("unroll")                                               \
            for (int mt = 0; mt < 2; mt++) {                                \
                const uint4& lo = (buf)[mt * 2 + 0];                        \
                const uint4& hi = (buf)[mt * 2 + 1];                        \
                mma16816(acc[mt][t], lo.x, hi.x, lo.y, hi.y, bw.x, bw.y);   \
                mma16816(acc[mt][t], lo.z, hi.z, lo.w, hi.w, bw.z, bw.w);   \
            }                                                               \
        }                                                                   \
    } while (0)

    for (int tile = blockIdx.x; tile < ntiles; tile += gridDim.x) {
        const int i0 = tile * MBLOCK;

        __syncthreads();   // previous tile's readers done before nbr_s overwrite
        // Stage neighbor byte-offsets (idx*64), coalesced, tail-guarded.
        if (is64) {
            const long long* nbr = (const long long*)nbr_raw;
            for (int t = tid; t < MBLOCK * KTAPS; t += NTHREADS) {
                int r = t / KTAPS;
                long long v = (i0 + r < n) ? __ldcs(nbr + (size_t)i0 * KTAPS + t) : 0;
                nbr_s[t] = ((int)v) << 6;
            }
        } else {
            const int* nbr = (const int*)nbr_raw;
            for (int t = tid; t < MBLOCK * KTAPS; t += NTHREADS) {
                int r = t / KTAPS;
                int v = (i0 + r < n) ? __ldcs(nbr + (size_t)i0 * KTAPS + t) : 0;
                nbr_s[t] = v << 6;
            }
        }
        __syncthreads();

        // Acc init = bias
        float acc[2][4][4];
        #pragma unroll
        for (int t = 0; t < 4; t++) {
            #pragma unroll
            for (int mt = 0; mt < 2; mt++) {
                acc[mt][t][0] = bz[t].x; acc[mt][t][1] = bz[t].y;
                acc[mt][t][2] = bz[t].x; acc[mt][t][3] = bz[t].y;
            }
        }

        // Depth-3 software pipeline, 4 rotating register buffers, fully unrolled
        // so all buffer indices are compile-time constants.
        uint4 A[4][4];
        LOAD_TAP(A[0], 0);
        LOAD_TAP(A[1], 1);
        LOAD_TAP(A[2], 2);

        #pragma unroll
        for (int k = 0; k < KTAPS; k++) {
            if (k + 3 < KTAPS) LOAD_TAP(A[(k + 3) & 3], k + 3);
            MMA_TAP(A[k & 3], k);
        }

        // Epilogue: streaming stores (bias already in acc)
        #pragma unroll
        for (int mt = 0; mt < 2; mt++) {
            #pragma unroll
            for (int half = 0; half < 2; half++) {
                int r = i0 + mb + mt * 16 + nrow + half * 8;
                if (r < n) {
                    float* po = out + (size_t)r * COUT + 2 * q;
                    #pragma unroll
                    for (int t = 0; t < 4; t++) {
                        float2 v;
                        v.x = acc[mt][t][half * 2 + 0];
                        v.y = acc[mt][t][half * 2 + 1];
                        __stcs((float2*)(po + t * 8), v);
                    }
                }
            }
        }
    }
}

// ---------------- Launch ----------------
extern "C" void kernel_launch(void* const* d_in, const int* in_sizes, int n_in,
                              void* d_out, int out_size) {
    const float* x    = (const float*)d_in[0];       // [N, 32] f32
    const float* w    = (const float*)d_in[1];       // [27, 32, 32] f32
    const float* bias = (const float*)d_in[2];       // [32] f32
    const void*  nbr  = d_in[3];                     // [N, 27] int32 OR int64 (detected)
    float*       out  = (float*)d_out;               // [N, 32] f32

    const int n = in_sizes[0] / CIN;
    const int ntiles = (n + MBLOCK - 1) / MBLOCK;

    int nsm = 148;
    cudaDeviceGetAttribute(&nsm, cudaDevAttrMultiProcessorCount, 0);
    int grid = 2 * nsm;
    if (grid > ntiles) grid = ntiles;

    cudaFuncSetAttribute(conv_main_kernel,
                         cudaFuncAttributeMaxDynamicSharedMemorySize, SMEM_BYTES);

    {
        long long total = (long long)n * 16;
        int blocks = (int)((total + 255) / 256);
        prep_kernel<<<blocks, 256>>>(x, w, (const int*)nbr, n);
    }
    conv_main_kernel<<<grid, NTHREADS, SMEM_BYTES>>>(nbr, bias, out, n, ntiles);
}